// round 1
// baseline (speedup 1.0000x reference)
#include <cuda_runtime.h>
#include <cstddef>

// Problem constants (fixed-shape benchmark)
#define VV   2048
#define NN   16
#define DI   32
#define DO   64
#define NH   8
#define NT   1152          // tasks = H*12*12
#define CID  192           // DI*6
#define EDIM 2496          // 32*13*6
#define MROW 29952         // 12*EDIM
#define KA_ELEMS (DO*VV*6)     // 786432
#define FM_ELEMS (DI*VV*6)     // 393216

// ---------------- constant tables ----------------
__constant__ int cINV[12][6] = {
    {0,1,2,3,4,5},{0,5,4,3,2,1},{4,3,0,5,2,1},{1,2,4,3,5,0},
    {3,5,2,0,4,1},{1,4,3,5,0,2},{4,0,3,1,2,5},{1,0,2,4,3,5},
    {4,1,2,5,0,3},{3,1,4,0,2,5},{2,1,4,5,3,0},{4,5,0,3,1,2}};
__constant__ int cROLL[5][6] = {
    {0,1,2,3,4,5},{0,2,3,4,5,1},{0,3,4,5,1,2},{0,4,5,1,2,3},{0,5,1,2,3,4}};
__constant__ int cC2V[6][2] = {{0,1},{6,7},{2,11},{4,9},{5,8},{3,10}};
#define PHI 1.6180339887498949f
__constant__ float cVSU[12][3] = {
    {0.f,1.f,PHI},{0.f,1.f,-PHI},{0.f,-1.f,PHI},{0.f,-1.f,-PHI},
    {1.f,PHI,0.f},{1.f,-PHI,0.f},{-1.f,PHI,0.f},{-1.f,-PHI,0.f},
    {PHI,0.f,1.f},{PHI,0.f,-1.f},{-PHI,0.f,1.f},{-PHI,0.f,-1.f}};

// ---------------- device scratch ----------------
__device__ float g_Wdr[CID * NT];                 // [ci][task], task=h*144+k*12+r, includes 0.5 scale
__device__ float g_Wg[12 * DO * EDIM];            // [r][d][e], e=(c*13+k)*6+i
__device__ float g_M[(size_t)VV * MROW];          // [p][r][e]
__device__ float g_feat[12 * DO * VV];            // [r][d][p]

// ---------------- symmetry expansion ----------------
__device__ __forceinline__ float w13v(const float* Wp, int k, int j) {
    if (k == 0)  return (j == 0) ? Wp[0] : Wp[1];
    if (k == 1)  return (j == 0) ? Wp[2] : Wp[3];
    if (k == 12) return (j == 0) ? Wp[4] : Wp[5];
    if (k < 7)   return Wp[6  + cROLL[k - 2][j]];
    return               Wp[12 + cROLL[k - 7][j]];
}

__global__ void prepWdr(const float* __restrict__ Wdir) {
    int idx = blockIdx.x * blockDim.x + threadIdx.x;
    if (idx >= CID * NT) return;
    int t = idx % NT, ci = idx / NT;
    int c = ci / 6, i = ci % 6;
    int h = t / 144, k = (t / 12) % 12, r = t % 12;
    const float* Wp = Wdir + (h * 32 + c) * 18;
    g_Wdr[idx] = 0.5f * w13v(Wp, k, cINV[r][i]);   // fold 1/sqrt(dph)=0.5
}

__global__ void prepWg(const float* __restrict__ W) {
    int idx = blockIdx.x * blockDim.x + threadIdx.x;
    if (idx >= 12 * DO * EDIM) return;
    int e = idx % EDIM;
    int d = (idx / EDIM) % DO;
    int r = idx / (EDIM * DO);
    int c = e / 78, rem = e % 78, k = rem / 6, i = rem % 6;
    const float* Wp = W + (d * 32 + c) * 18;
    g_Wg[idx] = w13v(Wp, k, cINV[r][i]);
}

// ---------------- kernel A: per-vertex cross / act / softmax / M ----------------
__global__ __launch_bounds__(192) void kernA(const int* __restrict__ nbr_idx,
                                             const float* __restrict__ verts,
                                             const float* __restrict__ fm,
                                             const float* __restrict__ wdim) {
    const int p = blockIdx.x;
    const int tid = threadIdx.x;
    __shared__ __align__(16) float s_cross[CID * 16];   // [ci][n]
    __shared__ __align__(16) float s_wdim[33 * 32];
    __shared__ float s_de[16 * 6];
    __shared__ int s_nbr[16];

    for (int t = tid; t < 33 * 32; t += 192) s_wdim[t] = wdim[t];

    if (tid < 16) {
        int nb = nbr_idx[p * NN + tid];
        s_nbr[tid] = nb;
        float px = verts[p * 3], py = verts[p * 3 + 1], pz = verts[p * 3 + 2];
        float dx = verts[nb * 3] - px;
        float dy = verts[nb * 3 + 1] - py;
        float dz = verts[nb * 3 + 2] - pz;
        float nrm = sqrtf(dx * dx + dy * dy + dz * dz);
        float inv = 1.0f / fmaxf(nrm, 1e-12f);
        dx *= inv; dy *= inv; dz *= inv;
        const float invn = rsqrtf(2.0f + PHI);
        float d0[12];
#pragma unroll
        for (int v = 0; v < 12; v++)
            d0[v] = (cVSU[v][0] * dx + cVSU[v][1] * dy + cVSU[v][2] * dz) * invn;
#pragma unroll
        for (int col = 0; col < 6; col++)
            s_de[tid * 6 + col] = fmaxf(d0[cC2V[col][0]], d0[cC2V[col][1]]);
    }
    __syncthreads();

    if (tid < 96) {
        // cross[o,n,i] = sum_c W_dim[c,o]*nf[c,n,i] + W_dim[32,o]*de[n,i]
        int n = tid / 6, i = tid % 6;
        int nb = s_nbr[n];
        float acc[32];
#pragma unroll
        for (int o = 0; o < 32; o++) acc[o] = 0.f;
        for (int c = 0; c < 33; c++) {
            float v = (c < 32) ? fm[((size_t)c * VV + nb) * 6 + i] : s_de[n * 6 + i];
            const float4* wd4 = (const float4*)&s_wdim[c * 32];
#pragma unroll
            for (int q = 0; q < 8; q++) {
                float4 w = wd4[q];
                acc[4 * q + 0] += w.x * v;
                acc[4 * q + 1] += w.y * v;
                acc[4 * q + 2] += w.z * v;
                acc[4 * q + 3] += w.w * v;
            }
        }
#pragma unroll
        for (int o = 0; o < 32; o++) s_cross[(o * 6 + i) * 16 + n] = acc[o];
    } else {
        // k=12 slice of M: center features (feature_map of this vertex), all 12 r
        int t0 = tid - 96;
        for (int jj = 0; jj < 2; jj++) {
            int idx = t0 + 96 * jj;            // 0..191
            int c = idx / 6, i = idx % 6;
            float v = fm[((size_t)c * VV + p) * 6 + i];
            size_t base = (size_t)p * MROW + (size_t)(c * 13 + 12) * 6 + i;
#pragma unroll
            for (int r = 0; r < 12; r++) g_M[base + (size_t)r * EDIM] = v;
        }
    }
    __syncthreads();

    const float4* cs4 = (const float4*)s_cross;

    // act tasks: (h,k,r) = 1152; register-block 2 tasks (h, h+4) per thread; 3 outer iters
    for (int it = 0; it < 3; it++) {
        int t = tid + 192 * it;               // 0..575
        int h0 = t / 144;
        int k  = (t / 12) % 12;
        int r  = t % 12;
        float a0[16], a1[16];
#pragma unroll
        for (int n = 0; n < 16; n++) { a0[n] = 0.f; a1[n] = 0.f; }
        const float* wp = g_Wdr + t;
#pragma unroll 2
        for (int ci = 0; ci < CID; ci++) {
            float w0 = wp[ci * NT];
            float w1 = wp[ci * NT + 576];
#pragma unroll
            for (int q = 0; q < 4; q++) {
                float4 cv = cs4[ci * 4 + q];
                a0[4 * q + 0] += w0 * cv.x; a0[4 * q + 1] += w0 * cv.y;
                a0[4 * q + 2] += w0 * cv.z; a0[4 * q + 3] += w0 * cv.w;
                a1[4 * q + 0] += w1 * cv.x; a1[4 * q + 1] += w1 * cv.y;
                a1[4 * q + 2] += w1 * cv.z; a1[4 * q + 3] += w1 * cv.w;
            }
        }
        // softmax over n + M = sum_n a[n]*cross[c,n,i], for both tasks
#pragma unroll
        for (int half = 0; half < 2; half++) {
            float* a = (half == 0) ? a0 : a1;
            int h = h0 + 4 * half;
            float m = a[0];
#pragma unroll
            for (int n = 1; n < 16; n++) m = fmaxf(m, a[n]);
            float s = 0.f;
#pragma unroll
            for (int n = 0; n < 16; n++) { a[n] = __expf(a[n] - m); s += a[n]; }
            float invs = 1.0f / s;
#pragma unroll
            for (int n = 0; n < 16; n++) a[n] *= invs;
            size_t base = (size_t)p * MROW + (size_t)r * EDIM;
#pragma unroll
            for (int cc = 0; cc < 4; cc++) {
                int c = h * 4 + cc;
                float mv[6];
#pragma unroll
                for (int i = 0; i < 6; i++) {
                    const float4* cp = cs4 + (c * 6 + i) * 4;
                    float4 x0 = cp[0], x1 = cp[1], x2 = cp[2], x3 = cp[3];
                    float s2 = a[0] * x0.x + a[1] * x0.y + a[2] * x0.z + a[3] * x0.w
                             + a[4] * x1.x + a[5] * x1.y + a[6] * x1.z + a[7] * x1.w
                             + a[8] * x2.x + a[9] * x2.y + a[10] * x2.z + a[11] * x2.w
                             + a[12] * x3.x + a[13] * x3.y + a[14] * x3.z + a[15] * x3.w;
                    mv[i] = s2;
                }
                float* dst = &g_M[base + (size_t)(c * 13 + k) * 6];
                float2* dst2 = (float2*)dst;
                dst2[0] = make_float2(mv[0], mv[1]);
                dst2[1] = make_float2(mv[2], mv[3]);
                dst2[2] = make_float2(mv[4], mv[5]);
            }
        }
    }
}

// ---------------- kernel B: feat[r] (64 x 2048) = Wg[r] (64 x 2496) @ M (2496 x 2048) ----------------
__global__ __launch_bounds__(256) void kernB() {
    const int r  = blockIdx.y;
    const int p0 = blockIdx.x * 64;
    const int tid = threadIdx.x;
    __shared__ __align__(16) float Wt[2][16][64];
    __shared__ __align__(16) float Mt[2][16][64];

    const int ld = tid & 63, lj = tid >> 6;          // loader: row ld, chunk lj
    const float* wbase = g_Wg + ((size_t)r * DO + ld) * EDIM;
    const float* mbase = g_M + (size_t)(p0 + ld) * MROW + (size_t)r * EDIM;

    const int px = tid & 15, dx = tid >> 4;          // compute: 4d x 4p per thread
    float acc[4][4];
#pragma unroll
    for (int a = 0; a < 4; a++)
#pragma unroll
        for (int b = 0; b < 4; b++) acc[a][b] = 0.f;

    // prologue
    {
        float4 wv = *(const float4*)(wbase + 4 * lj);
        float4 mv = *(const float4*)(mbase + 4 * lj);
        Wt[0][4 * lj + 0][ld] = wv.x; Wt[0][4 * lj + 1][ld] = wv.y;
        Wt[0][4 * lj + 2][ld] = wv.z; Wt[0][4 * lj + 3][ld] = wv.w;
        Mt[0][4 * lj + 0][ld] = mv.x; Mt[0][4 * lj + 1][ld] = mv.y;
        Mt[0][4 * lj + 2][ld] = mv.z; Mt[0][4 * lj + 3][ld] = mv.w;
    }
    __syncthreads();

    int buf = 0;
    const int NSTEP = EDIM / 16;   // 156
    for (int s = 0; s < NSTEP; s++) {
        if (s + 1 < NSTEP) {
            int e0 = (s + 1) * 16;
            float4 wv = *(const float4*)(wbase + e0 + 4 * lj);
            float4 mv = *(const float4*)(mbase + e0 + 4 * lj);
            int nb = buf ^ 1;
            Wt[nb][4 * lj + 0][ld] = wv.x; Wt[nb][4 * lj + 1][ld] = wv.y;
            Wt[nb][4 * lj + 2][ld] = wv.z; Wt[nb][4 * lj + 3][ld] = wv.w;
            Mt[nb][4 * lj + 0][ld] = mv.x; Mt[nb][4 * lj + 1][ld] = mv.y;
            Mt[nb][4 * lj + 2][ld] = mv.z; Mt[nb][4 * lj + 3][ld] = mv.w;
        }
#pragma unroll
        for (int e = 0; e < 16; e++) {
            float4 w = *(const float4*)&Wt[buf][e][dx * 4];
            float4 m = *(const float4*)&Mt[buf][e][px * 4];
            acc[0][0] += w.x * m.x; acc[0][1] += w.x * m.y; acc[0][2] += w.x * m.z; acc[0][3] += w.x * m.w;
            acc[1][0] += w.y * m.x; acc[1][1] += w.y * m.y; acc[1][2] += w.y * m.z; acc[1][3] += w.y * m.w;
            acc[2][0] += w.z * m.x; acc[2][1] += w.z * m.y; acc[2][2] += w.z * m.z; acc[2][3] += w.z * m.w;
            acc[3][0] += w.w * m.x; acc[3][1] += w.w * m.y; acc[3][2] += w.w * m.z; acc[3][3] += w.w * m.w;
        }
        __syncthreads();
        buf ^= 1;
    }

#pragma unroll
    for (int dy = 0; dy < 4; dy++) {
        float4 o = make_float4(acc[dy][0], acc[dy][1], acc[dy][2], acc[dy][3]);
        *(float4*)&g_feat[((size_t)r * DO + dx * 4 + dy) * VV + p0 + px * 4] = o;
    }
}

// ---------------- kernel C: ka = max over C2V pairs of feat ----------------
__global__ void kernC(float* __restrict__ out) {
    int idx = blockIdx.x * blockDim.x + threadIdx.x;   // over DO*VV
    if (idx >= DO * VV) return;
    int d = idx / VV, p = idx % VV;
#pragma unroll
    for (int col = 0; col < 6; col++) {
        int r0 = cC2V[col][0], r1 = cC2V[col][1];
        float v = fmaxf(g_feat[((size_t)r0 * DO + d) * VV + p],
                        g_feat[((size_t)r1 * DO + d) * VV + p]);
        out[(size_t)idx * 6 + col] = v;
    }
}

extern "C" void kernel_launch(void* const* d_in, const int* in_sizes, int n_in,
                              void* d_out, int out_size) {
    const int*   nbr   = (const int*)d_in[0];
    const float* verts = (const float*)d_in[1];
    const float* fm    = (const float*)d_in[2];
    const float* wdim  = (const float*)d_in[3];
    const float* W     = (const float*)d_in[4];
    const float* Wdir  = (const float*)d_in[5];
    float* out = (float*)d_out;

    prepWdr<<<(CID * NT + 255) / 256, 256>>>(Wdir);
    prepWg<<<(12 * DO * EDIM + 255) / 256, 256>>>(W);
    kernA<<<VV, 192>>>(nbr, verts, fm, wdim);
    dim3 gb(VV / 64, 12);
    kernB<<<gb, 256>>>();
    kernC<<<(DO * VV + 255) / 256, 256>>>(out);
    if (out_size >= KA_ELEMS + FM_ELEMS) {
        cudaMemcpyAsync(out + KA_ELEMS, fm, (size_t)FM_ELEMS * sizeof(float),
                        cudaMemcpyDeviceToDevice, 0);
    }
}